// round 15
// baseline (speedup 1.0000x reference)
#include <cuda_runtime.h>
#include <cstdint>

#define CRF_B 512
#define CRF_S 1024
#define CRF_T 64
#define CHUNK 16
#define NCHUNK (CRF_S / CHUNK)     /* 64 */
#define RPC 4                       /* rows per CTA */
#define TPR 64                      /* threads per row (2 warps) */
#define NCTA (CRF_B / RPC)          /* 128 */

__device__ float g_partial[CRF_B];
__device__ int   g_count = 0;

typedef unsigned long long u64;

__device__ __forceinline__ float ex2f(float x) {
    float r; asm("ex2.approx.f32 %0, %1;" : "=f"(r) : "f"(x)); return r;
}
__device__ __forceinline__ float lg2f(float x) {
    float r; asm("lg2.approx.f32 %0, %1;" : "=f"(r) : "f"(x)); return r;
}
__device__ __forceinline__ u64 pack2(float lo, float hi) {
    u64 r; asm("mov.b64 %0, {%1, %2};" : "=l"(r) : "f"(lo), "f"(hi)); return r;
}
__device__ __forceinline__ void unpack2(u64 v, float& lo, float& hi) {
    asm("mov.b64 {%0, %1}, %2;" : "=f"(lo), "=f"(hi) : "l"(v));
}
__device__ __forceinline__ u64 ffma2(u64 a, u64 b, u64 c) {
    u64 d; asm("fma.rn.f32x2 %0, %1, %2, %3;" : "=l"(d) : "l"(a), "l"(b), "l"(c));
    return d;
}
__device__ __forceinline__ void cp16(uint32_t dst, const void* src) {
    asm volatile("cp.async.cg.shared.global [%0], [%1], 16;" :: "r"(dst), "l"(src));
}

// sizeof MUST be a multiple of 16 so row[1..3] keep 16-byte alignment for
// LDS.128 / cp.async.16 (R13 fault: 8972-byte stride).
struct __align__(16) RowSmem {
    float sEm[2][CHUNK][CRF_T];     // 8 KB
    float sMk[2][CHUNK];
    int   sTg[2][CHUNK];
    float sE[2][CRF_T];             // double-buffered E
    float sP0;                      // col-0 P published at odd steps
    float sRed[2];                  // epilogue cross-warp reduce
    float pad_;                     // -> 16-aligned stride
};
static_assert(sizeof(RowSmem) % 16 == 0, "RowSmem stride must be 16B-aligned");

// row barrier: both warps of row w rendezvous (named barrier id = w)
#define ROWBAR() asm volatile("bar.sync %0, %1;" :: "r"(w), "r"(TPR) : "memory")

// One recurrence step. PAR = parity of global step s (compile-time per copy).
// Thread owns ONE column wl: dot over ALL 64 states = 32 ffma2 (16 u64-pairs).
// Rescale: thread 0 publishes P0 at PAR==1; all threads extract/apply at PAR==0.
#define STEP(IDX, CB, PAR) do {                                               \
    ROWBAR();                                                                 \
    float _em = R.sEm[(CB)][(IDX)][wl];                                       \
    float _mk = R.sMk[(CB)][(IDX)];                                           \
    float _mkl = _mk * LOG2E;                                                 \
    float _ed;                                                                \
    if ((PAR) == 0) {                                                         \
        float _p0 = R.sP0;                                                    \
        int _u = (__float_as_int(_p0) >> 23) - 127;                           \
        sexp += _u;                                                           \
        _ed = ex2f(fmaf(_em, _mkl, (float)(-_u)));                            \
    } else {                                                                  \
        _ed = ex2f(_em * _mkl);                                               \
    }                                                                         \
    const ulonglong2* _E2 = reinterpret_cast<const ulonglong2*>(R.sE[(PAR)]); \
    u64 _a = 0ull, _b = 0ull;                                                 \
    _Pragma("unroll")                                                         \
    for (int _k = 0; _k < 16; _k++) {                                         \
        ulonglong2 _v = _E2[_k];                                              \
        _a = ffma2(_v.x, tcp[2 * _k],     _a);                                \
        _b = ffma2(_v.y, tcp[2 * _k + 1], _b);                                \
    }                                                                         \
    float _xa, _ya, _xb, _yb;                                                 \
    unpack2(_a, _xa, _ya); unpack2(_b, _xb, _yb);                             \
    float _P = (_xa + _ya) + (_xb + _yb);                                     \
    R.sE[(PAR) ^ 1][wl] = _P * _ed;                                           \
    if ((PAR) == 1) { if (wl == 0) R.sP0 = _P; }                              \
} while (0)

// Per-chunk gold prologue: threads 0..15 of the row each own one step.
#define GOLD(CB, C) do {                                                      \
    int   _tgc = 0, _tgp = 0;                                                 \
    float _mkc = 0.f, _gec = 0.f, _gtc = 0.f;                                 \
    if (wl < CHUNK) {                                                         \
        _tgc = R.sTg[(CB)][wl];                                               \
        _tgp = (wl == 0) ? tagBound : R.sTg[(CB)][wl - 1];                    \
        _mkc = R.sMk[(CB)][wl];                                               \
        _gec = R.sEm[(CB)][wl][_tgc];                                         \
        if (!((C) == 0 && wl == 0))                                           \
            _gtc = __ldg(trans + _tgc * CRF_T + _tgp);                        \
    }                                                                         \
    tagBound = R.sTg[(CB)][CHUNK - 1];                                        \
    g = fmaf(_gtc + _gec, _mkc, g);                                           \
} while (0)

__global__ __launch_bounds__(RPC * TPR, 1)
void crf_main(const float* __restrict__ emis,
              const int*   __restrict__ tags,
              const float* __restrict__ mask,
              const float* __restrict__ trans,
              float* __restrict__ out)
{
    const int w   = threadIdx.x / TPR;       // row within CTA
    const int wl  = threadIdx.x % TPR;       // column index 0..63
    const int wir = wl >> 5;                 // warp within row (0/1)
    const int b   = blockIdx.x * RPC + w;

    __shared__ __align__(16) RowSmem row[RPC];
    RowSmem& R = row[w];

    const float LOG2E = 1.4426950408889634f;
    const float LN2   = 0.6931471805599453f;

    const float* mb    = mask + (size_t)b * CRF_S;
    const int*   tb    = tags + (size_t)b * CRF_S;
    const float* ebase = emis + (size_t)b * CRF_S * CRF_T;

    // ---- cp.async chunk issuer: 64 threads stage 16 steps ------------------
    auto issue_chunk = [&](int c) {
        const int    cb  = c & 1;
        const float* src = ebase + (size_t)c * CHUNK * CRF_T;
        uint32_t d0 = (uint32_t)__cvta_generic_to_shared(&R.sEm[cb][0][0]);
        #pragma unroll
        for (int k = 0; k < 4; k++) {           // 256 sixteen-byte units
            int u = k * TPR + wl;
            cp16(d0 + u * 16, src + u * 4);
        }
        if (wl < 4) {
            uint32_t dm = (uint32_t)__cvta_generic_to_shared(&R.sMk[cb][0]);
            cp16(dm + wl * 16, mb + c * CHUNK + wl * 4);
        } else if (wl < 8) {
            uint32_t dt = (uint32_t)__cvta_generic_to_shared(&R.sTg[cb][0]);
            cp16(dt + (wl - 4) * 16, tb + c * CHUNK + (wl - 4) * 4);
        }
        asm volatile("cp.async.commit_group;" ::: "memory");
    };

    issue_chunk(0);
    issue_chunk(1);

    // -------- Texp column wl as i-pair-packed f32x2 (32 u64 regs) ----------
    u64 tcp[CRF_T / 2];
    #pragma unroll
    for (int k = 0; k < CRF_T / 2; k++) {
        float a = ex2f(trans[(2 * k)     * CRF_T + wl] * LOG2E);
        float c = ex2f(trans[(2 * k + 1) * CRF_T + wl] * LOG2E);
        tcp[k] = pack2(a, c);
    }

    // ---------------- init (step 0) ----------------
    float mk0 = mb[0];
    float s0  = ebase[wl] * mk0;
    const float C0 = ebase[0] * mk0;            // col-0 score: uniform load

    // E(1) into buffer 1 (step s reads sE[s&1])
    R.sE[1][wl] = ex2f((s0 - C0) * LOG2E);

    int   sexp = 0;          // sum of applied power-of-2 exponents (uniform)
    float g    = 0.f;        // gold partials (threads 0..15)
    int   tagBound = 0;

    // ---------------- chunk 0 peeled: steps s = 1..15 ----------------
    {
        asm volatile("cp.async.wait_group 1;" ::: "memory");
        ROWBAR();
        GOLD(0, 0);
        #pragma unroll 4
        for (int k = 1; k < 16; k++)
            STEP(k, 0, (k & 1));
        issue_chunk(2);
    }

    // ---------------- chunks 1..62 ----------------
    for (int c = 1; c < NCHUNK - 1; ++c) {
        asm volatile("cp.async.wait_group 1;" ::: "memory");
        ROWBAR();
        const int cb = c & 1;
        GOLD(cb, c);
        #pragma unroll 4
        for (int k = 0; k < 16; k++)
            STEP(k, cb, (k & 1));
        if (c + 2 < NCHUNK) issue_chunk(c + 2);
    }

    // ---------------- chunk 63: steps 1008..1022 ----------------
    {
        asm volatile("cp.async.wait_group 0;" ::: "memory");
        ROWBAR();
        GOLD(1, NCHUNK - 1);
        #pragma unroll 4
        for (int k = 0; k < 15; k++)
            STEP(k, 1, (k & 1));
    }

    // ---------------- peeled last step (s = 1023, odd, reads buf 1) ---------
    {
        float em = R.sEm[1][15][wl];
        float mk = R.sMk[1][15];

        ROWBAR();

        const ulonglong2* E2 = reinterpret_cast<const ulonglong2*>(R.sE[1]);
        u64 a = 0ull, bb = 0ull;
        #pragma unroll
        for (int k = 0; k < 16; k++) {
            ulonglong2 v = E2[k];
            a  = ffma2(v.x, tcp[2 * k],     a);
            bb = ffma2(v.y, tcp[2 * k + 1], bb);
        }
        float xa, ya, xb, yb;
        unpack2(a, xa, ya); unpack2(bb, xb, yb);
        float P = (xa + ya) + (xb + yb);

        // t_j = P_j * exp(em_j * mk); score_j = C + log(t_j)
        float t = P * ex2f(em * mk * LOG2E);

        // sum over 64 columns: warp reduce + cross-warp via smem
        #pragma unroll
        for (int off = 16; off; off >>= 1)
            t += __shfl_xor_sync(0xffffffffu, t, off);
        if ((wl & 31) == 0) R.sRed[wir] = t;

        // gold: reduce thread partials (warp 0 holds all nonzero terms)
        #pragma unroll
        for (int off = 16; off; off >>= 1)
            g += __shfl_xor_sync(0xffffffffu, g, off);

        ROWBAR();

        if (wl == 0) {
            float tsum = R.sRed[0] + R.sRed[1];
            float C    = fmaf((float)sexp, LN2, C0);
            float fwd  = fmaf(lg2f(tsum), LN2, C);
            g_partial[b] = fwd - g;
        }
    }

    // ---------------- last-arriving row reduces the mean ---------------------
    bool last = false;
    if (wl == 0) {
        __threadfence();
        int c = atomicAdd(&g_count, 1);
        last = (c == CRF_B - 1);
        if (last) g_count = 0;              // reset for graph replay
    }
    last = __shfl_sync(0xffffffffu, last, 0);   // warp 0 of the row
    if (last && wir == 0) {
        __threadfence();
        int l = wl & 31;
        float v = 0.f;
        #pragma unroll
        for (int i = 0; i < CRF_B / 32; i++)
            v += g_partial[i * 32 + l];
        #pragma unroll
        for (int off = 16; off; off >>= 1)
            v += __shfl_xor_sync(0xffffffffu, v, off);
        if (l == 0) out[0] = v * (1.0f / CRF_B);
    }
}

extern "C" void kernel_launch(void* const* d_in, const int* in_sizes, int n_in,
                              void* d_out, int out_size)
{
    const float* emis  = (const float*)d_in[0];
    const int*   tags  = (const int*)  d_in[1];
    const float* mask  = (const float*)d_in[2];
    const float* trans = (const float*)d_in[3];

    crf_main<<<NCTA, RPC * TPR>>>(emis, tags, mask, trans, (float*)d_out);
}

// round 16
// speedup vs baseline: 1.2890x; 1.2890x over previous
#include <cuda_runtime.h>
#include <cstdint>

#define CRF_B 512
#define CRF_S 1024
#define CRF_T 64
#define CHUNK 16
#define NCHUNK (CRF_S / CHUNK)     /* 64 */
#define RPC 4                       /* rows (warps) per CTA */
#define NCTA (CRF_B / RPC)          /* 128 */

__device__ float g_partial[CRF_B];
__device__ int   g_count = 0;

typedef unsigned long long u64;

__device__ __forceinline__ float ex2f(float x) {
    float r; asm("ex2.approx.f32 %0, %1;" : "=f"(r) : "f"(x)); return r;
}
__device__ __forceinline__ float lg2f(float x) {
    float r; asm("lg2.approx.f32 %0, %1;" : "=f"(r) : "f"(x)); return r;
}
__device__ __forceinline__ u64 pack2(float lo, float hi) {
    u64 r; asm("mov.b64 %0, {%1, %2};" : "=l"(r) : "f"(lo), "f"(hi)); return r;
}
__device__ __forceinline__ void unpack2(u64 v, float& lo, float& hi) {
    asm("mov.b64 {%0, %1}, %2;" : "=f"(lo), "=f"(hi) : "l"(v));
}
__device__ __forceinline__ u64 ffma2(u64 a, u64 b, u64 c) {
    u64 d; asm("fma.rn.f32x2 %0, %1, %2, %3;" : "=l"(d) : "l"(a), "l"(b), "l"(c));
    return d;
}
__device__ __forceinline__ void cp16(uint32_t dst, const void* src) {
    asm volatile("cp.async.cg.shared.global [%0], [%1], 16;" :: "r"(dst), "l"(src));
}

struct __align__(16) RowSmem {      // stride multiple of 16 (R13 lesson)
    float sEm[2][CHUNK][CRF_T];     // 8 KB
    float sMk[2][CHUNK];
    int   sTg[2][CHUNK];
    float sE[2][CRF_T];             // double-buffered E
};
static_assert(sizeof(RowSmem) % 16 == 0, "RowSmem stride must be 16B-aligned");

// Compiler-only ordering fence. The warp is fully convergent in the step loop
// (no branches); per-thread LDS/STS order through the in-order LSU provides
// the cross-lane ordering that __syncwarp provided (every ladder read range
// overlaps the lane's own prior store, so ptxas cannot reorder them either).
#define WSOFT() asm volatile("" ::: "memory")

// One recurrence step. PAR = parity of global step s (compile-time per copy).
// Lane owns columns c0=2l, c0+1. Rescale: extract exponent at PAR==1 (shfl,
// also a convergence anchor), apply as exact ex2 addend at PAR==0.
#define STEP(IDX, CB, PAR) do {                                               \
    WSOFT();                                                                  \
    float2 _em = *reinterpret_cast<const float2*>(&R.sEm[(CB)][(IDX)][c0]);   \
    float  _mk = R.sMk[(CB)][(IDX)];                                          \
    float _mkl = _mk * LOG2E;                                                 \
    float _ed0, _ed1;                                                         \
    if ((PAR) == 0) { _ed0 = ex2f(fmaf(_em.x, _mkl, du));                     \
                      _ed1 = ex2f(fmaf(_em.y, _mkl, du)); }                   \
    else            { _ed0 = ex2f(_em.x * _mkl);                              \
                      _ed1 = ex2f(_em.y * _mkl); }                            \
    const ulonglong2* _E2 = reinterpret_cast<const ulonglong2*>(R.sE[(PAR)]); \
    u64 _a = 0ull, _b = 0ull;                                                 \
    _Pragma("unroll")                                                         \
    for (int _k = 0; _k < 16; _k++) {                                         \
        ulonglong2 _v = _E2[_k];                                              \
        _a = ffma2(_v.x, tA[2 * _k],     _a);                                 \
        _b = ffma2(_v.x, tB[2 * _k],     _b);                                 \
        _a = ffma2(_v.y, tA[2 * _k + 1], _a);                                 \
        _b = ffma2(_v.y, tB[2 * _k + 1], _b);                                 \
    }                                                                         \
    float _xa, _ya, _xb, _yb;                                                 \
    unpack2(_a, _xa, _ya); unpack2(_b, _xb, _yb);                             \
    float _P0 = _xa + _ya, _P1 = _xb + _yb;                                   \
    *reinterpret_cast<float2*>(&R.sE[(PAR) ^ 1][c0]) =                        \
        make_float2(_P0 * _ed0, _P1 * _ed1);                                  \
    if ((PAR) == 1) {                                                         \
        float _P0b = __shfl_sync(0xffffffffu, _P0, 0);                        \
        int _u = (__float_as_int(_P0b) >> 23) - 127;                          \
        sexp += _u;                                                           \
        du = (float)(-_u);                                                    \
    }                                                                         \
} while (0)

// Gold loads issued at chunk head (lanes 0..15, one step each); the fmaf that
// consumes the LDG happens AFTER the 16 steps (latency fully hidden).
#define GOLD_LOAD(CB, C) do {                                                 \
    gT = 0.f; gE = 0.f; gM = 0.f;                                             \
    if (l < CHUNK) {                                                          \
        int _tgc = R.sTg[(CB)][l];                                            \
        int _tgp = (l == 0) ? tagBound : R.sTg[(CB)][l - 1];                  \
        gM = R.sMk[(CB)][l];                                                  \
        gE = R.sEm[(CB)][l][_tgc];                                            \
        if (!((C) == 0 && l == 0))                                            \
            gT = __ldg(trans + _tgc * CRF_T + _tgp);                          \
    }                                                                         \
    tagBound = R.sTg[(CB)][CHUNK - 1];                                        \
} while (0)

#define GOLD_ACC() do { g = fmaf(gT + gE, gM, g); } while (0)

__global__ __launch_bounds__(32 * RPC, 1)
void crf_main(const float* __restrict__ emis,
              const int*   __restrict__ tags,
              const float* __restrict__ mask,
              const float* __restrict__ trans,
              float* __restrict__ out)
{
    const int w  = threadIdx.x >> 5;     // warp = row-within-CTA
    const int l  = threadIdx.x & 31;     // lane; owns columns 2l, 2l+1
    const int b  = blockIdx.x * RPC + w;
    const int c0 = 2 * l;

    __shared__ __align__(16) RowSmem row[RPC];
    RowSmem& R = row[w];

    const float LOG2E = 1.4426950408889634f;
    const float LN2   = 0.6931471805599453f;

    const float* mb    = mask + (size_t)b * CRF_S;
    const int*   tb    = tags + (size_t)b * CRF_S;
    const float* ebase = emis + (size_t)b * CRF_S * CRF_T;

    // ---- cp.async chunk issuer (chunk c covers steps [16c, 16c+16)) --------
    auto issue_chunk = [&](int c) {
        const int    cb  = c & 1;
        const float* src = ebase + (size_t)c * CHUNK * CRF_T;
        uint32_t d0 = (uint32_t)__cvta_generic_to_shared(&R.sEm[cb][0][0]);
        #pragma unroll
        for (int k = 0; k < 8; k++) {           // 256 sixteen-byte units
            int u = k * 32 + l;
            cp16(d0 + u * 16, src + u * 4);
        }
        if (l < 4) {
            uint32_t dm = (uint32_t)__cvta_generic_to_shared(&R.sMk[cb][0]);
            cp16(dm + l * 16, mb + c * CHUNK + l * 4);
        } else if (l < 8) {
            uint32_t dt = (uint32_t)__cvta_generic_to_shared(&R.sTg[cb][0]);
            cp16(dt + (l - 4) * 16, tb + c * CHUNK + (l - 4) * 4);
        }
        asm volatile("cp.async.commit_group;" ::: "memory");
    };

    // strictly 2 chunks in flight
    issue_chunk(0);
    issue_chunk(1);

    // -------- Texp columns c0, c0+1 as i-pair-packed f32x2 (64 u64 regs) ----
    u64 tA[CRF_T / 2], tB[CRF_T / 2];
    #pragma unroll
    for (int k = 0; k < CRF_T / 2; k++) {
        float2 r0 = *reinterpret_cast<const float2*>(trans + (2 * k)     * CRF_T + c0);
        float2 r1 = *reinterpret_cast<const float2*>(trans + (2 * k + 1) * CRF_T + c0);
        tA[k] = pack2(ex2f(r0.x * LOG2E), ex2f(r1.x * LOG2E));
        tB[k] = pack2(ex2f(r0.y * LOG2E), ex2f(r1.y * LOG2E));
    }

    // ---------------- init (step 0) ----------------
    float  mk0 = mb[0];
    float2 ev0 = *reinterpret_cast<const float2*>(ebase + c0);
    float s0 = ev0.x * mk0;
    float s1 = ev0.y * mk0;

    const float C0 = __shfl_sync(0xffffffffu, s0, 0);   // log-space base offset

    // E(1) into buffer 1 (step s reads sE[s&1])
    *reinterpret_cast<float2*>(&R.sE[1][c0]) =
        make_float2(ex2f((s0 - C0) * LOG2E), ex2f((s1 - C0) * LOG2E));

    float du   = 0.f;        // exact power-of-2 log2-addend (applied even s)
    int   sexp = 0;          // sum of applied exponents (uniform across lanes)
    float g    = 0.f;        // gold partials (lanes 0..15)
    int   tagBound = 0;
    float gT, gE, gM;        // deferred gold-term registers

    // ---------------- chunk 0 peeled: steps s = 1..15 ----------------
    {
        asm volatile("cp.async.wait_group 1;" ::: "memory");
        __syncwarp();
        GOLD_LOAD(0, 0);
        #pragma unroll 4
        for (int k = 1; k < 16; k++)
            STEP(k, 0, (k & 1));
        GOLD_ACC();
        __syncwarp();                      // bound lane drift before buffer reuse
        issue_chunk(2);
    }

    // ---------------- chunks 1..62 ----------------
    for (int c = 1; c < NCHUNK - 1; ++c) {
        asm volatile("cp.async.wait_group 1;" ::: "memory");
        __syncwarp();
        const int cb = c & 1;
        GOLD_LOAD(cb, c);
        #pragma unroll 4
        for (int k = 0; k < 16; k++)
            STEP(k, cb, (k & 1));          // s = 16c+k, parity = k&1
        GOLD_ACC();
        __syncwarp();
        if (c + 2 < NCHUNK) issue_chunk(c + 2);
    }

    // ---------------- chunk 63: steps s = 1008..1022 ----------------
    {
        asm volatile("cp.async.wait_group 0;" ::: "memory");
        __syncwarp();
        GOLD_LOAD(1, NCHUNK - 1);          // covers s = 1008..1023 incl. last
        #pragma unroll 4
        for (int k = 0; k < 15; k++)
            STEP(k, 1, (k & 1));
        GOLD_ACC();
    }

    // ---------------- peeled last step (s = 1023, reads buf 1) --------------
    {
        float2 em = *reinterpret_cast<const float2*>(&R.sEm[1][15][c0]);
        float  mk = R.sMk[1][15];

        __syncwarp();

        const ulonglong2* E2 = reinterpret_cast<const ulonglong2*>(R.sE[1]);
        u64 a = 0ull, bb = 0ull;
        #pragma unroll
        for (int k = 0; k < 16; k++) {
            ulonglong2 v = E2[k];
            a  = ffma2(v.x, tA[2 * k],     a);
            bb = ffma2(v.x, tB[2 * k],     bb);
            a  = ffma2(v.y, tA[2 * k + 1], a);
            bb = ffma2(v.y, tB[2 * k + 1], bb);
        }
        float xa, ya, xb, yb;
        unpack2(a, xa, ya); unpack2(bb, xb, yb);

        // t_j = P_j * exp(em_j * mk); score_j = C + log(t_j)
        float mkl = mk * LOG2E;
        float t0 = (xa + ya) * ex2f(em.x * mkl);
        float t1 = (xb + yb) * ex2f(em.y * mkl);

        float tsum = t0 + t1;
        #pragma unroll
        for (int off = 16; off; off >>= 1)
            tsum += __shfl_xor_sync(0xffffffffu, tsum, off);

        // gold: reduce lane partials
        #pragma unroll
        for (int off = 16; off; off >>= 1)
            g += __shfl_xor_sync(0xffffffffu, g, off);

        if (l == 0) {
            float C   = fmaf((float)sexp, LN2, C0);
            float fwd = fmaf(lg2f(tsum), LN2, C);
            g_partial[b] = fwd - g;
        }
    }

    // ---------------- last-arriving warp reduces the mean --------------------
    bool last = false;
    if (l == 0) {
        __threadfence();
        int c = atomicAdd(&g_count, 1);
        last = (c == CRF_B - 1);
        if (last) g_count = 0;              // reset for graph replay
    }
    last = __shfl_sync(0xffffffffu, last, 0);
    if (last) {
        __threadfence();
        float v = 0.f;
        #pragma unroll
        for (int i = 0; i < CRF_B / 32; i++)
            v += g_partial[i * 32 + l];
        #pragma unroll
        for (int off = 16; off; off >>= 1)
            v += __shfl_xor_sync(0xffffffffu, v, off);
        if (l == 0) out[0] = v * (1.0f / CRF_B);
    }
}

extern "C" void kernel_launch(void* const* d_in, const int* in_sizes, int n_in,
                              void* d_out, int out_size)
{
    const float* emis  = (const float*)d_in[0];
    const int*   tags  = (const int*)  d_in[1];
    const float* mask  = (const float*)d_in[2];
    const float* trans = (const float*)d_in[3];

    crf_main<<<NCTA, 32 * RPC>>>(emis, tags, mask, trans, (float*)d_out);
}

// round 17
// speedup vs baseline: 1.4676x; 1.1386x over previous
#include <cuda_runtime.h>
#include <cstdint>

#define CRF_B 512
#define CRF_S 1024
#define CRF_T 64
#define CHUNK 16
#define NCHUNK (CRF_S / CHUNK)     /* 64 */
#define RPC 4                       /* rows (warps) per CTA */
#define NCTA (CRF_B / RPC)          /* 128 */

__device__ float g_partial[CRF_B];
__device__ int   g_count = 0;

__device__ __forceinline__ float ex2f(float x) {
    float r; asm("ex2.approx.f32 %0, %1;" : "=f"(r) : "f"(x)); return r;
}
__device__ __forceinline__ float lg2f(float x) {
    float r; asm("lg2.approx.f32 %0, %1;" : "=f"(r) : "f"(x)); return r;
}
// bf16x2 packed ops: single 32-bit registers -> rt=2 (no 3-bank conflict
// like the 64-bit f32x2 form, which measured rt=3).
__device__ __forceinline__ unsigned hfma2b(unsigned a, unsigned b, unsigned c) {
    unsigned d; asm("fma.rn.bf16x2 %0, %1, %2, %3;" : "=r"(d) : "r"(a), "r"(b), "r"(c));
    return d;
}
__device__ __forceinline__ unsigned hadd2b(unsigned a, unsigned b) {
    unsigned d; asm("add.rn.bf16x2 %0, %1, %2;" : "=r"(d) : "r"(a), "r"(b));
    return d;
}
__device__ __forceinline__ float bflo(unsigned r) { return __int_as_float(r << 16); }
__device__ __forceinline__ float bfhi(unsigned r) { return __int_as_float(r & 0xffff0000u); }
// pack two fp32 -> bf16x2 {lo, hi} (first cvt source is the HIGH half)
__device__ __forceinline__ unsigned bf2(float lo, float hi) {
    unsigned r; asm("cvt.rn.bf16x2.f32 %0, %1, %2;" : "=r"(r) : "f"(hi), "f"(lo));
    return r;
}
__device__ __forceinline__ void cp16(uint32_t dst, const void* src) {
    asm volatile("cp.async.cg.shared.global [%0], [%1], 16;" :: "r"(dst), "l"(src));
}

struct __align__(16) RowSmem {      // stride multiple of 16 (R13 lesson)
    float    sEm[2][CHUNK][CRF_T];  // 8 KB fp32 emissions
    float    sMk[2][CHUNK];
    int      sTg[2][CHUNK];
    unsigned sE16[2][CRF_T / 2];    // double-buffered E, bf16x2 i-pairs (256 B)
};
static_assert(sizeof(RowSmem) % 16 == 0, "RowSmem stride must be 16B-aligned");

#define WSOFT() asm volatile("" ::: "memory")

// One step. PAR = parity of global step s (compile-time). Lane owns columns
// c0=2l, c0+1. Dot in bf16x2 (4 accumulator chains), combine + rescale fp32.
#define STEP(IDX, CB, PAR) do {                                               \
    WSOFT();                                                                  \
    float2 _em = *reinterpret_cast<const float2*>(&R.sEm[(CB)][(IDX)][c0]);   \
    float  _mk = R.sMk[(CB)][(IDX)];                                          \
    float _mkl = _mk * LOG2E;                                                 \
    float _ed0, _ed1;                                                         \
    if ((PAR) == 0) { _ed0 = ex2f(fmaf(_em.x, _mkl, du));                     \
                      _ed1 = ex2f(fmaf(_em.y, _mkl, du)); }                   \
    else            { _ed0 = ex2f(_em.x * _mkl);                              \
                      _ed1 = ex2f(_em.y * _mkl); }                            \
    const uint4* _E4 = reinterpret_cast<const uint4*>(R.sE16[(PAR)]);         \
    unsigned _a0 = 0u, _a1 = 0u, _b0 = 0u, _b1 = 0u;                          \
    _Pragma("unroll")                                                         \
    for (int _k = 0; _k < 8; _k++) {                                          \
        uint4 _v = _E4[_k];                                                   \
        _a0 = hfma2b(_v.x, tA16[4 * _k],     _a0);                            \
        _b0 = hfma2b(_v.x, tB16[4 * _k],     _b0);                            \
        _a1 = hfma2b(_v.y, tA16[4 * _k + 1], _a1);                            \
        _b1 = hfma2b(_v.y, tB16[4 * _k + 1], _b1);                            \
        _a0 = hfma2b(_v.z, tA16[4 * _k + 2], _a0);                            \
        _b0 = hfma2b(_v.z, tB16[4 * _k + 2], _b0);                            \
        _a1 = hfma2b(_v.w, tA16[4 * _k + 3], _a1);                            \
        _b1 = hfma2b(_v.w, tB16[4 * _k + 3], _b1);                            \
    }                                                                         \
    unsigned _as = hadd2b(_a0, _a1), _bs = hadd2b(_b0, _b1);                  \
    float _P0 = bflo(_as) + bfhi(_as);                                        \
    float _P1 = bflo(_bs) + bfhi(_bs);                                        \
    R.sE16[(PAR) ^ 1][l] = bf2(_P0 * _ed0, _P1 * _ed1);                       \
    if ((PAR) == 1) {                                                         \
        float _P0b = __shfl_sync(0xffffffffu, _P0, 0);                        \
        int _u = (__float_as_int(_P0b) >> 23) - 127;                          \
        sexp += _u;                                                           \
        du = (float)(-_u);                                                    \
    }                                                                         \
} while (0)

// Gold loads at chunk head (lanes 0..15), consumed after the 16 steps.
#define GOLD_LOAD(CB, C) do {                                                 \
    gT = 0.f; gE = 0.f; gM = 0.f;                                             \
    if (l < CHUNK) {                                                          \
        int _tgc = R.sTg[(CB)][l];                                            \
        int _tgp = (l == 0) ? tagBound : R.sTg[(CB)][l - 1];                  \
        gM = R.sMk[(CB)][l];                                                  \
        gE = R.sEm[(CB)][l][_tgc];                                            \
        if (!((C) == 0 && l == 0))                                            \
            gT = __ldg(trans + _tgc * CRF_T + _tgp);                          \
    }                                                                         \
    tagBound = R.sTg[(CB)][CHUNK - 1];                                        \
} while (0)

#define GOLD_ACC() do { g = fmaf(gT + gE, gM, g); } while (0)

__global__ __launch_bounds__(32 * RPC, 1)
void crf_main(const float* __restrict__ emis,
              const int*   __restrict__ tags,
              const float* __restrict__ mask,
              const float* __restrict__ trans,
              float* __restrict__ out)
{
    const int w  = threadIdx.x >> 5;     // warp = row-within-CTA
    const int l  = threadIdx.x & 31;     // lane; owns columns 2l, 2l+1
    const int b  = blockIdx.x * RPC + w;
    const int c0 = 2 * l;

    __shared__ __align__(16) RowSmem row[RPC];
    RowSmem& R = row[w];

    const float LOG2E = 1.4426950408889634f;
    const float LN2   = 0.6931471805599453f;

    const float* mb    = mask + (size_t)b * CRF_S;
    const int*   tb    = tags + (size_t)b * CRF_S;
    const float* ebase = emis + (size_t)b * CRF_S * CRF_T;

    // ---- cp.async chunk issuer (chunk c covers steps [16c, 16c+16)) --------
    auto issue_chunk = [&](int c) {
        const int    cb  = c & 1;
        const float* src = ebase + (size_t)c * CHUNK * CRF_T;
        uint32_t d0 = (uint32_t)__cvta_generic_to_shared(&R.sEm[cb][0][0]);
        #pragma unroll
        for (int k = 0; k < 8; k++) {           // 256 sixteen-byte units
            int u = k * 32 + l;
            cp16(d0 + u * 16, src + u * 4);
        }
        if (l < 4) {
            uint32_t dm = (uint32_t)__cvta_generic_to_shared(&R.sMk[cb][0]);
            cp16(dm + l * 16, mb + c * CHUNK + l * 4);
        } else if (l < 8) {
            uint32_t dt = (uint32_t)__cvta_generic_to_shared(&R.sTg[cb][0]);
            cp16(dt + (l - 4) * 16, tb + c * CHUNK + (l - 4) * 4);
        }
        asm volatile("cp.async.commit_group;" ::: "memory");
    };

    // strictly 2 chunks in flight
    issue_chunk(0);
    issue_chunk(1);

    // -------- Texp columns c0, c0+1 as bf16x2 i-pairs (64 x 32-bit regs) ----
    unsigned tA16[CRF_T / 2], tB16[CRF_T / 2];
    #pragma unroll
    for (int k = 0; k < CRF_T / 2; k++) {
        float2 r0 = *reinterpret_cast<const float2*>(trans + (2 * k)     * CRF_T + c0);
        float2 r1 = *reinterpret_cast<const float2*>(trans + (2 * k + 1) * CRF_T + c0);
        tA16[k] = bf2(ex2f(r0.x * LOG2E), ex2f(r1.x * LOG2E));
        tB16[k] = bf2(ex2f(r0.y * LOG2E), ex2f(r1.y * LOG2E));
    }

    // ---------------- init (step 0) ----------------
    float  mk0 = mb[0];
    float2 ev0 = *reinterpret_cast<const float2*>(ebase + c0);
    float s0 = ev0.x * mk0;
    float s1 = ev0.y * mk0;

    const float C0 = __shfl_sync(0xffffffffu, s0, 0);   // log-space base offset

    // E(1) into buffer 1 (step s reads sE16[s&1]); lane packs its i-pair
    R.sE16[1][l] = bf2(ex2f((s0 - C0) * LOG2E), ex2f((s1 - C0) * LOG2E));

    float du   = 0.f;        // exact power-of-2 log2-addend (applied even s)
    int   sexp = 0;          // sum of applied exponents (uniform across lanes)
    float g    = 0.f;        // gold partials (lanes 0..15)
    int   tagBound = 0;
    float gT, gE, gM;        // deferred gold-term registers

    // ---------------- chunk 0 peeled: steps s = 1..15 ----------------
    {
        asm volatile("cp.async.wait_group 1;" ::: "memory");
        __syncwarp();
        GOLD_LOAD(0, 0);
        #pragma unroll 4
        for (int k = 1; k < 16; k++)
            STEP(k, 0, (k & 1));
        GOLD_ACC();
        __syncwarp();                      // bound lane drift before buffer reuse
        issue_chunk(2);
    }

    // ---------------- chunks 1..62 ----------------
    for (int c = 1; c < NCHUNK - 1; ++c) {
        asm volatile("cp.async.wait_group 1;" ::: "memory");
        __syncwarp();
        const int cb = c & 1;
        GOLD_LOAD(cb, c);
        #pragma unroll 4
        for (int k = 0; k < 16; k++)
            STEP(k, cb, (k & 1));          // s = 16c+k, parity = k&1
        GOLD_ACC();
        __syncwarp();
        if (c + 2 < NCHUNK) issue_chunk(c + 2);
    }

    // ---------------- chunk 63: steps s = 1008..1022 ----------------
    {
        asm volatile("cp.async.wait_group 0;" ::: "memory");
        __syncwarp();
        GOLD_LOAD(1, NCHUNK - 1);          // covers s = 1008..1023 incl. last
        #pragma unroll 4
        for (int k = 0; k < 15; k++)
            STEP(k, 1, (k & 1));
        GOLD_ACC();
    }

    // ---------------- peeled last step (s = 1023, reads buf 1) --------------
    {
        float2 em = *reinterpret_cast<const float2*>(&R.sEm[1][15][c0]);
        float  mk = R.sMk[1][15];

        __syncwarp();

        const uint4* E4 = reinterpret_cast<const uint4*>(R.sE16[1]);
        unsigned a0 = 0u, a1 = 0u, b0 = 0u, b1 = 0u;
        #pragma unroll
        for (int k = 0; k < 8; k++) {
            uint4 v = E4[k];
            a0 = hfma2b(v.x, tA16[4 * k],     a0);
            b0 = hfma2b(v.x, tB16[4 * k],     b0);
            a1 = hfma2b(v.y, tA16[4 * k + 1], a1);
            b1 = hfma2b(v.y, tB16[4 * k + 1], b1);
            a0 = hfma2b(v.z, tA16[4 * k + 2], a0);
            b0 = hfma2b(v.z, tB16[4 * k + 2], b0);
            a1 = hfma2b(v.w, tA16[4 * k + 3], a1);
            b1 = hfma2b(v.w, tB16[4 * k + 3], b1);
        }
        unsigned as = hadd2b(a0, a1), bs = hadd2b(b0, b1);
        float P0 = bflo(as) + bfhi(as);
        float P1 = bflo(bs) + bfhi(bs);

        // t_j = P_j * exp(em_j * mk); score_j = C + log(t_j)
        float mkl = mk * LOG2E;
        float t0 = P0 * ex2f(em.x * mkl);
        float t1 = P1 * ex2f(em.y * mkl);

        float tsum = t0 + t1;
        #pragma unroll
        for (int off = 16; off; off >>= 1)
            tsum += __shfl_xor_sync(0xffffffffu, tsum, off);

        // gold: reduce lane partials
        #pragma unroll
        for (int off = 16; off; off >>= 1)
            g += __shfl_xor_sync(0xffffffffu, g, off);

        if (l == 0) {
            float C   = fmaf((float)sexp, LN2, C0);
            float fwd = fmaf(lg2f(tsum), LN2, C);
            g_partial[b] = fwd - g;
        }
    }

    // ---------------- last-arriving warp reduces the mean --------------------
    bool last = false;
    if (l == 0) {
        __threadfence();
        int c = atomicAdd(&g_count, 1);
        last = (c == CRF_B - 1);
        if (last) g_count = 0;              // reset for graph replay
    }
    last = __shfl_sync(0xffffffffu, last, 0);
    if (last) {
        __threadfence();
        float v = 0.f;
        #pragma unroll
        for (int i = 0; i < CRF_B / 32; i++)
            v += g_partial[i * 32 + l];
        #pragma unroll
        for (int off = 16; off; off >>= 1)
            v += __shfl_xor_sync(0xffffffffu, v, off);
        if (l == 0) out[0] = v * (1.0f / CRF_B);
    }
}

extern "C" void kernel_launch(void* const* d_in, const int* in_sizes, int n_in,
                              void* d_out, int out_size)
{
    const float* emis  = (const float*)d_in[0];
    const int*   tags  = (const int*)  d_in[1];
    const float* mask  = (const float*)d_in[2];
    const float* trans = (const float*)d_in[3];

    crf_main<<<NCTA, 32 * RPC>>>(emis, tags, mask, trans, (float*)d_out);
}